// round 2
// baseline (speedup 1.0000x reference)
#include <cuda_runtime.h>
#include <math.h>

// Problem constants (fixed by the reference setup_inputs).
#define BB 2048      // number of query rows (B)
#define CC 2048      // feature dim (C)
#define NN 16384     // support rows (Bs*TOPK)
#define INV_TEMP 20.0f

// Tiling
#define BM 64
#define BN 64
#define BK 16
#define NSPLIT (NN / BN)   // 256 column-blocks

// Scratch (allocation-free rule: __device__ globals)
__device__ float g_pmin[BB * NSPLIT];   // 2 MB
__device__ float g_nsum[BB * NSPLIT];   // 2 MB
__device__ float g_loss[BB];

// ---------------------------------------------------------------------------
// Fused GEMM + epilogue: each CTA computes a 64x64 tile of E = exp(S/T),
// reduces per-row (min over positives, sum over negatives) within the tile,
// and writes deterministic per-(row, col-block) partials.
// ---------------------------------------------------------------------------
__global__ __launch_bounds__(256, 2)
void gemm_reduce_kernel(const float* __restrict__ feats,
                        const float* __restrict__ fs,
                        const int*   __restrict__ labels,
                        const int*   __restrict__ labels_s)
{
    __shared__ float As[BK][BM];
    __shared__ float Bs[BK][BN];
    __shared__ float red_min[BM][16];
    __shared__ float red_sum[BM][16];

    const int nblk = blockIdx.x;        // 0..255
    const int mblk = blockIdx.y;        // 0..31
    const int row0 = mblk * BM;
    const int col0 = nblk * BN;
    const int tid  = threadIdx.x;
    const int tx   = tid & 15;          // 0..15  -> 4 cols each
    const int ty   = tid >> 4;          // 0..15  -> 4 rows each

    // global load mapping: each thread loads one float4 of A and one of B
    const int lr  = tid >> 2;           // tile row 0..63
    const int lk4 = (tid & 3) * 4;      // k offset within BK

    const float* Aptr = feats + (size_t)(row0 + lr) * CC + lk4;
    const float* Bptr = fs    + (size_t)(col0 + lr) * CC + lk4;

    float acc[4][4];
    #pragma unroll
    for (int i = 0; i < 4; ++i)
        #pragma unroll
        for (int j = 0; j < 4; ++j) acc[i][j] = 0.0f;

    for (int k0 = 0; k0 < CC; k0 += BK) {
        float4 av = *(const float4*)(Aptr + k0);
        float4 bv = *(const float4*)(Bptr + k0);
        __syncthreads();  // previous iteration's shared reads done
        As[lk4 + 0][lr] = av.x;
        As[lk4 + 1][lr] = av.y;
        As[lk4 + 2][lr] = av.z;
        As[lk4 + 3][lr] = av.w;
        Bs[lk4 + 0][lr] = bv.x;
        Bs[lk4 + 1][lr] = bv.y;
        Bs[lk4 + 2][lr] = bv.z;
        Bs[lk4 + 3][lr] = bv.w;
        __syncthreads();

        #pragma unroll
        for (int kk = 0; kk < BK; ++kk) {
            float4 a = *(const float4*)&As[kk][ty * 4];
            float4 b = *(const float4*)&Bs[kk][tx * 4];
            acc[0][0] += a.x * b.x; acc[0][1] += a.x * b.y;
            acc[0][2] += a.x * b.z; acc[0][3] += a.x * b.w;
            acc[1][0] += a.y * b.x; acc[1][1] += a.y * b.y;
            acc[1][2] += a.y * b.z; acc[1][3] += a.y * b.w;
            acc[2][0] += a.z * b.x; acc[2][1] += a.z * b.y;
            acc[2][2] += a.z * b.z; acc[2][3] += a.z * b.w;
            acc[3][0] += a.w * b.x; acc[3][1] += a.w * b.y;
            acc[3][2] += a.w * b.z; acc[3][3] += a.w * b.w;
        }
    }

    // Epilogue: exp + label-partitioned row reduction
    int labr[4], labc[4];
    #pragma unroll
    for (int i = 0; i < 4; ++i) labr[i] = labels[row0 + ty * 4 + i];
    #pragma unroll
    for (int j = 0; j < 4; ++j) labc[j] = labels_s[col0 + tx * 4 + j];

    #pragma unroll
    for (int i = 0; i < 4; ++i) {
        float pmin = INFINITY;
        float nsum = 0.0f;
        #pragma unroll
        for (int j = 0; j < 4; ++j) {
            float e = expf(acc[i][j] * INV_TEMP);
            if (labr[i] == labc[j]) pmin = fminf(pmin, e);
            else                    nsum += e;
        }
        red_min[ty * 4 + i][tx] = pmin;
        red_sum[ty * 4 + i][tx] = nsum;
    }
    __syncthreads();

    if (tid < BM) {
        float m = INFINITY, s = 0.0f;
        #pragma unroll
        for (int t = 0; t < 16; ++t) {
            m = fminf(m, red_min[tid][t]);
            s += red_sum[tid][t];
        }
        g_pmin[(size_t)(row0 + tid) * NSPLIT + nblk] = m;
        g_nsum[(size_t)(row0 + tid) * NSPLIT + nblk] = s;
    }
}

// ---------------------------------------------------------------------------
// Per-row partial reduction -> per-row loss (deterministic ordered sums)
// ---------------------------------------------------------------------------
__global__ void row_loss_kernel()
{
    int row = blockIdx.x * blockDim.x + threadIdx.x;
    if (row >= BB) return;
    const float* pm = g_pmin + (size_t)row * NSPLIT;
    const float* ns = g_nsum + (size_t)row * NSPLIT;
    float m = INFINITY, s = 0.0f;
    #pragma unroll 8
    for (int t = 0; t < NSPLIT; ++t) {
        m = fminf(m, pm[t]);
        s += ns[t];
    }
    g_loss[row] = -logf(m / (m + s + 1e-6f) + 1e-6f);
}

// ---------------------------------------------------------------------------
// Final mean over B rows -> scalar output
// ---------------------------------------------------------------------------
__global__ void mean_kernel(float* __restrict__ out)
{
    __shared__ float red[256];
    int tid = threadIdx.x;
    float s = 0.0f;
    for (int r = tid; r < BB; r += 256) s += g_loss[r];
    red[tid] = s;
    __syncthreads();
    for (int off = 128; off > 0; off >>= 1) {
        if (tid < off) red[tid] += red[tid + off];
        __syncthreads();
    }
    if (tid == 0) out[0] = red[0] / (float)BB;
}

extern "C" void kernel_launch(void* const* d_in, const int* in_sizes, int n_in,
                              void* d_out, int out_size)
{
    const float* feats    = (const float*)d_in[0];
    const float* feats_s  = (const float*)d_in[1];   // [16384, 2048] after reshape
    const int*   labels   = (const int*)d_in[2];
    const int*   labels_s = (const int*)d_in[3];
    float* out = (float*)d_out;

    dim3 grid(NSPLIT, BB / BM);   // (256, 32)
    gemm_reduce_kernel<<<grid, 256>>>(feats, feats_s, labels, labels_s);
    row_loss_kernel<<<BB / 256, 256>>>();
    mean_kernel<<<1, 256>>>(out);
}

// round 5
// speedup vs baseline: 4.3407x; 4.3407x over previous
#include <cuda_runtime.h>
#include <cuda_bf16.h>
#include <math.h>
#include <stdint.h>

// ---------------- problem constants ----------------
#define BB 2048
#define CC 2048
#define NN 16384
#define INV_TEMP 20.0f
#define SCALE_LOG2E 28.853900817779268f   // (1/0.05) * log2(e)

// ---------------- tiling (tcgen05 path) ----------------
#define BM 128
#define BN 256
#define BKC 64                 // bf16 K elems per chunk (128 bytes per row)
#define NCHUNK (CC / BKC)      // 32
#define NSPL 128               // partial slots per row: 64 nblk * 2 halves
#define STAGE_BYTES 49152      // A(16K) + B0(16K) + B1(16K)
#define DSMEM_BYTES (2 * STAGE_BYTES + 1024)

// ---------------- device scratch (no runtime alloc allowed) ----------------
__device__ __nv_bfloat16 g_A[BB * CC];      // 8 MB
__device__ __nv_bfloat16 g_B[NN * CC];      // 64 MB
__device__ float g_pmin[BB * NSPL];
__device__ float g_nsum[BB * NSPL];
__device__ float g_loss[BB];

// Select tcgen05 path only when compiling an arch/family-specific target
// (sm_103a). The generic compute_103 pass gets a plain-SASS fallback so ptxas
// never sees tcgen05 on .target sm_103.
#if defined(__CUDA_ARCH__) && (__CUDA_ARCH__ >= 1000) && \
    (defined(__CUDA_ARCH_FEAT_SM103_ALL) || defined(__CUDA_ARCH_SPECIFIC__) || \
     defined(__CUDA_ARCH_FAMILY_SPECIFIC__))
#define USE_TCGEN05 1
#else
#define USE_TCGEN05 0
#endif

// ---------------- fp32 -> bf16 conversion ----------------
__global__ void cvtA_kernel(const float4* __restrict__ in) {
    int i = blockIdx.x * blockDim.x + threadIdx.x;
    if (i < BB * CC / 4) {
        float4 v = in[i];
        __nv_bfloat162* o = (__nv_bfloat162*)g_A;
        o[2 * i]     = __floats2bfloat162_rn(v.x, v.y);
        o[2 * i + 1] = __floats2bfloat162_rn(v.z, v.w);
    }
}
__global__ void cvtB_kernel(const float4* __restrict__ in) {
    int i = blockIdx.x * blockDim.x + threadIdx.x;
    if (i < NN * CC / 4) {
        float4 v = in[i];
        __nv_bfloat162* o = (__nv_bfloat162*)g_B;
        o[2 * i]     = __floats2bfloat162_rn(v.x, v.y);
        o[2 * i + 1] = __floats2bfloat162_rn(v.z, v.w);
    }
}

#if USE_TCGEN05
// ===========================================================================
// tcgen05 path (sm_103a specific)
// ===========================================================================
__device__ __forceinline__ uint32_t smem_u32(const void* p) {
    uint32_t a;
    asm("{ .reg .u64 t; cvta.to.shared.u64 t, %1; cvt.u32.u64 %0, t; }" : "=r"(a) : "l"(p));
    return a;
}
__device__ __forceinline__ uint32_t elect_one() {
    uint32_t p;
    asm volatile("{ .reg .pred p; elect.sync _|p, 0xFFFFFFFF; selp.b32 %0, 1, 0, p; }" : "=r"(p));
    return p;
}
__device__ __forceinline__ float ex2f(float x) {
    float y; asm("ex2.approx.f32 %0, %1;" : "=f"(y) : "f"(x)); return y;
}

#define MBARRIER_INIT(addr, cnt) \
    asm volatile("mbarrier.init.shared.b64 [%0], %1;" :: "r"(addr), "r"(cnt) : "memory")

#define MBARRIER_WAIT_PARITY(addr, par) do {                                   \
    uint32_t _m = (addr), _p = (par), _d;                                      \
    asm volatile("{ .reg .pred p;"                                             \
        "mbarrier.try_wait.parity.acquire.cta.shared::cta.b64 p, [%1], %2;"    \
        "selp.b32 %0, 1, 0, p; }" : "=r"(_d) : "r"(_m), "r"(_p) : "memory");   \
    if (!_d) {                                                                 \
        asm volatile("{ .reg .pred P1; WL_%=:"                                 \
        "mbarrier.try_wait.parity.acquire.cta.shared::cta.b64 P1, [%0], %1, 0x989680;" \
        "@P1 bra.uni WD_%=; bra.uni WL_%=; WD_%=: }"                           \
        :: "r"(_m), "r"(_p) : "memory");                                       \
    }                                                                          \
} while (0)

#define TCGEN05_ALLOC(slot, ncols) \
    asm volatile("tcgen05.alloc.cta_group::1.sync.aligned.shared::cta.b32 [%0], %1;" \
                 :: "r"(slot), "r"(ncols) : "memory")
#define TCGEN05_DEALLOC(tmem, ncols) \
    asm volatile("tcgen05.dealloc.cta_group::1.sync.aligned.b32 %0, %1;" :: "r"(tmem), "r"(ncols))
#define TCGEN05_RELINQ() \
    asm volatile("tcgen05.relinquish_alloc_permit.cta_group::1.sync.aligned;")
#define TCGEN05_COMMIT(mb) \
    asm volatile("tcgen05.commit.cta_group::1.mbarrier::arrive::one.shared::cluster.b64 [%0];" \
                 :: "r"(mb) : "memory")
#define TCGEN05_FENCE_AFTER() asm volatile("tcgen05.fence::after_thread_sync;" ::: "memory")
#define TCGEN05_WAIT_LD()     asm volatile("tcgen05.wait::ld.sync.aligned;" ::: "memory")

#define TCGEN05_LD_X32(r, addr) \
    asm volatile("tcgen05.ld.sync.aligned.32x32b.x32.b32 " \
        "{%0,%1,%2,%3,%4,%5,%6,%7,%8,%9,%10,%11,%12,%13,%14,%15," \
        "%16,%17,%18,%19,%20,%21,%22,%23,%24,%25,%26,%27,%28,%29,%30,%31}, [%32];" \
        : "=r"((r)[0]),"=r"((r)[1]),"=r"((r)[2]),"=r"((r)[3]),"=r"((r)[4]),"=r"((r)[5]), \
          "=r"((r)[6]),"=r"((r)[7]),"=r"((r)[8]),"=r"((r)[9]),"=r"((r)[10]),"=r"((r)[11]), \
          "=r"((r)[12]),"=r"((r)[13]),"=r"((r)[14]),"=r"((r)[15]),"=r"((r)[16]),"=r"((r)[17]), \
          "=r"((r)[18]),"=r"((r)[19]),"=r"((r)[20]),"=r"((r)[21]),"=r"((r)[22]),"=r"((r)[23]), \
          "=r"((r)[24]),"=r"((r)[25]),"=r"((r)[26]),"=r"((r)[27]),"=r"((r)[28]),"=r"((r)[29]), \
          "=r"((r)[30]),"=r"((r)[31]) : "r"(addr))

// idesc: f32 accum, bf16 A/B, N=128, M=128
#define IDESC ((1u << 4) | (1u << 7) | (1u << 10) | (16u << 17) | (8u << 24))

// SW128 K-major desc: LBO=1, SBO=64, version=1
__device__ __forceinline__ uint64_t make_desc(uint32_t addr) {
    return (2ull << 61) | (1ull << 46) | (64ull << 32) | (1ull << 16)
         | ((uint64_t)(addr >> 4) & 0x3FFF);
}
__device__ __forceinline__ uint32_t swz(uint32_t o) { return o ^ ((o >> 3) & 0x70); }

__device__ __forceinline__ void mma_f16_ss(uint32_t d, uint64_t a, uint64_t b,
                                           uint32_t idesc, uint32_t acc) {
    asm volatile("{ .reg .pred p; setp.ne.u32 p, %5, 0;"
        "tcgen05.mma.cta_group::1.kind::f16 [%0], %1, %2, %3, {%4,%4,%4,%4}, p; }"
        :: "r"(d), "l"(a), "l"(b), "r"(idesc), "r"(0u), "r"(acc) : "memory");
}

__global__ __launch_bounds__(256)
void gemm_kernel(const int* __restrict__ labels, const int* __restrict__ labels_s)
{
    extern __shared__ char dsm[];
    __shared__ uint64_t mbar[2];
    __shared__ uint32_t tmem_slot;
    __shared__ int slab[BN];

    const int nblk = blockIdx.x;           // 0..63
    const int mblk = blockIdx.y;           // 0..15
    const int row0 = mblk * BM;
    const int col0 = nblk * BN;
    const int tid  = threadIdx.x;
    const int wid  = tid >> 5;

    char* sm = (char*)(((uintptr_t)dsm + 1023) & ~(uintptr_t)1023);
    const uint32_t smb = smem_u32(sm);
    const uint32_t mb0 = smem_u32(&mbar[0]);
    const uint32_t mb1 = smem_u32(&mbar[1]);

    if (wid == 0) TCGEN05_ALLOC(smem_u32(&tmem_slot), 256);
    if (tid == 0) { MBARRIER_INIT(mb0, 1); MBARRIER_INIT(mb1, 1); }
    slab[tid] = labels_s[col0 + tid];
    __syncthreads();
    const uint32_t tmem = tmem_slot;

    const __nv_bfloat16* gArow = g_A + (size_t)row0 * CC;
    const __nv_bfloat16* gBrow = g_B + (size_t)col0 * CC;

    int ph0 = 0, ph1 = 0;
    for (int k = 0; k < NCHUNK; ++k) {
        const int buf = k & 1;
        if (k >= 2) {
            if (buf == 0) { MBARRIER_WAIT_PARITY(mb0, ph0); ph0 ^= 1; }
            else          { MBARRIER_WAIT_PARITY(mb1, ph1); ph1 ^= 1; }
        }
        const int kofs = k * BKC;
        char* stage = sm + buf * STAGE_BYTES;
        #pragma unroll
        for (int t = 0; t < 4; ++t) {
            int idx = tid + t * 256;
            int row = idx >> 3, seg = idx & 7;
            float4 v = *(const float4*)(gArow + (size_t)row * CC + kofs + seg * 8);
            *(float4*)(stage + swz(row * 128 + seg * 16)) = v;
        }
        #pragma unroll
        for (int t = 0; t < 8; ++t) {
            int idx = tid + t * 256;
            int row = idx >> 3, seg = idx & 7;
            float4 v = *(const float4*)(gBrow + (size_t)row * CC + kofs + seg * 8);
            uint32_t off = 16384 + (row >> 7) * 16384 + swz((row & 127) * 128 + seg * 16);
            *(float4*)(stage + off) = v;
        }
        asm volatile("fence.proxy.async.shared::cta;" ::: "memory");
        __syncthreads();

        if (wid == 0 && elect_one()) {
            uint32_t sb = smb + buf * STAGE_BYTES;
            uint64_t ad = make_desc(sb);
            uint64_t b0 = make_desc(sb + 16384);
            uint64_t b1 = make_desc(sb + 32768);
            #pragma unroll
            for (int ks = 0; ks < 4; ++ks) {
                uint32_t acc = (k > 0 || ks > 0) ? 1u : 0u;
                mma_f16_ss(tmem,       ad + ks * 2, b0 + ks * 2, IDESC, acc);
                mma_f16_ss(tmem + 128, ad + ks * 2, b1 + ks * 2, IDESC, acc);
            }
            TCGEN05_COMMIT(buf == 0 ? mb0 : mb1);
        }
    }
    MBARRIER_WAIT_PARITY(mb0, ph0);
    MBARRIER_WAIT_PARITY(mb1, ph1);
    TCGEN05_FENCE_AFTER();

    // ---- epilogue: warps 0-3 -> cols 0-127, warps 4-7 -> cols 128-255 ----
    const int half = tid >> 7;
    const int wg   = tid & 127;                       // D row
    const uint32_t woff = (uint32_t)(wg >> 5) << 21;  // TMEM lane-group
    const int lab = labels[row0 + wg];
    const uint32_t dbase = tmem + half * 128 + woff;

    float smin = INFINITY, nsum = 0.0f;
    #pragma unroll
    for (int cb = 0; cb < 4; ++cb) {
        uint32_t regs[32];
        TCGEN05_LD_X32(regs, dbase + cb * 32);
        TCGEN05_WAIT_LD();
        #pragma unroll
        for (int c = 0; c < 32; ++c) {
            float s = __uint_as_float(regs[c]);
            int cl = slab[half * 128 + cb * 32 + c];
            if (cl == lab) smin = fminf(smin, s);
            else           nsum += ex2f(s * SCALE_LOG2E);
        }
    }
    float pmin = ex2f(smin * SCALE_LOG2E);
    size_t slot = (size_t)(row0 + wg) * NSPL + nblk * 2 + half;
    g_pmin[slot] = pmin;
    g_nsum[slot] = nsum;

    __syncthreads();
    if (wid == 0) { TCGEN05_RELINQ(); TCGEN05_DEALLOC(tmem, 256); }
}

#else
// ===========================================================================
// Fallback path (plain sm_103 / compute_103 pass): SIMT tiled GEMM on the
// converted bf16 data. Same grid (64,16) x 256, same partial-slot layout.
// ===========================================================================
__global__ __launch_bounds__(256)
void gemm_kernel(const int* __restrict__ labels, const int* __restrict__ labels_s)
{
    __shared__ float As[16][64];
    __shared__ float Bs[16][64];
    __shared__ float red_min[64][16];
    __shared__ float red_sum[64][16];

    const int nblk = blockIdx.x;
    const int mblk = blockIdx.y;
    const int tid  = threadIdx.x;
    const int tx   = tid & 15;
    const int ty   = tid >> 4;
    const int lr   = tid >> 2;
    const int lk4  = (tid & 3) * 4;

    for (int msub = 0; msub < 2; ++msub) {
        const int row0 = mblk * 128 + msub * 64;
        int labr[4];
        #pragma unroll
        for (int i = 0; i < 4; ++i) labr[i] = labels[row0 + ty * 4 + i];

        for (int half = 0; half < 2; ++half) {
            float fm = INFINITY, fs = 0.0f;   // used by tid < 64
            for (int nsub = 0; nsub < 2; ++nsub) {
                const int col0 = nblk * 256 + half * 128 + nsub * 64;
                int labc[4];
                #pragma unroll
                for (int j = 0; j < 4; ++j) labc[j] = labels_s[col0 + tx * 4 + j];

                float acc[4][4];
                #pragma unroll
                for (int i = 0; i < 4; ++i)
                    #pragma unroll
                    for (int j = 0; j < 4; ++j) acc[i][j] = 0.0f;

                for (int k0 = 0; k0 < CC; k0 += 16) {
                    const __nv_bfloat162* ap = (const __nv_bfloat162*)
                        (g_A + (size_t)(row0 + lr) * CC + k0 + lk4);
                    const __nv_bfloat162* bp = (const __nv_bfloat162*)
                        (g_B + (size_t)(col0 + lr) * CC + k0 + lk4);
                    __nv_bfloat162 a01 = ap[0], a23 = ap[1];
                    __nv_bfloat162 b01 = bp[0], b23 = bp[1];
                    __syncthreads();
                    As[lk4 + 0][lr] = __bfloat162float(a01.x);
                    As[lk4 + 1][lr] = __bfloat162float(a01.y);
                    As[lk4 + 2][lr] = __bfloat162float(a23.x);
                    As[lk4 + 3][lr] = __bfloat162float(a23.y);
                    Bs[lk4 + 0][lr] = __bfloat162float(b01.x);
                    Bs[lk4 + 1][lr] = __bfloat162float(b01.y);
                    Bs[lk4 + 2][lr] = __bfloat162float(b23.x);
                    Bs[lk4 + 3][lr] = __bfloat162float(b23.y);
                    __syncthreads();
                    #pragma unroll
                    for (int kk = 0; kk < 16; ++kk) {
                        float4 a = *(const float4*)&As[kk][ty * 4];
                        float4 b = *(const float4*)&Bs[kk][tx * 4];
                        acc[0][0] += a.x * b.x; acc[0][1] += a.x * b.y;
                        acc[0][2] += a.x * b.z; acc[0][3] += a.x * b.w;
                        acc[1][0] += a.y * b.x; acc[1][1] += a.y * b.y;
                        acc[1][2] += a.y * b.z; acc[1][3] += a.y * b.w;
                        acc[2][0] += a.z * b.x; acc[2][1] += a.z * b.y;
                        acc[2][2] += a.z * b.z; acc[2][3] += a.z * b.w;
                        acc[3][0] += a.w * b.x; acc[3][1] += a.w * b.y;
                        acc[3][2] += a.w * b.z; acc[3][3] += a.w * b.w;
                    }
                }

                #pragma unroll
                for (int i = 0; i < 4; ++i) {
                    float pmin = INFINITY, nsum = 0.0f;
                    #pragma unroll
                    for (int j = 0; j < 4; ++j) {
                        float e = expf(acc[i][j] * INV_TEMP);
                        if (labr[i] == labc[j]) pmin = fminf(pmin, e);
                        else                    nsum += e;
                    }
                    red_min[ty * 4 + i][tx] = pmin;
                    red_sum[ty * 4 + i][tx] = nsum;
                }
                __syncthreads();
                if (tid < 64) {
                    #pragma unroll
                    for (int t = 0; t < 16; ++t) {
                        fm = fminf(fm, red_min[tid][t]);
                        fs += red_sum[tid][t];
                    }
                }
                __syncthreads();
            }
            if (tid < 64) {
                size_t slot = (size_t)(row0 + tid) * NSPL + nblk * 2 + half;
                g_pmin[slot] = fm;
                g_nsum[slot] = fs;
            }
        }
    }
}
#endif  // USE_TCGEN05

// ---------------- per-row loss ----------------
__global__ void row_loss_kernel()
{
    int row = blockIdx.x * blockDim.x + threadIdx.x;
    if (row >= BB) return;
    const float* pm = g_pmin + (size_t)row * NSPL;
    const float* ns = g_nsum + (size_t)row * NSPL;
    float m = INFINITY, s = 0.0f;
    #pragma unroll 8
    for (int t = 0; t < NSPL; ++t) { m = fminf(m, pm[t]); s += ns[t]; }
    g_loss[row] = -logf(m / (m + s + 1e-6f) + 1e-6f);
}

// ---------------- mean ----------------
__global__ void mean_kernel(float* __restrict__ out)
{
    __shared__ float red[256];
    int tid = threadIdx.x;
    float s = 0.0f;
    for (int r = tid; r < BB; r += 256) s += g_loss[r];
    red[tid] = s;
    __syncthreads();
    for (int off = 128; off > 0; off >>= 1) {
        if (tid < off) red[tid] += red[tid + off];
        __syncthreads();
    }
    if (tid == 0) out[0] = red[0] / (float)BB;
}

extern "C" void kernel_launch(void* const* d_in, const int* in_sizes, int n_in,
                              void* d_out, int out_size)
{
    const float* feats    = (const float*)d_in[0];
    const float* feats_s  = (const float*)d_in[1];
    const int*   labels   = (const int*)d_in[2];
    const int*   labels_s = (const int*)d_in[3];
    float* out = (float*)d_out;

    static int attr_done = 0;
    if (!attr_done) {
        cudaFuncSetAttribute(gemm_kernel, cudaFuncAttributeMaxDynamicSharedMemorySize,
                             DSMEM_BYTES);
        attr_done = 1;
    }

    cvtA_kernel<<<(BB * CC / 4 + 255) / 256, 256>>>((const float4*)feats);
    cvtB_kernel<<<(NN * CC / 4 + 255) / 256, 256>>>((const float4*)feats_s);

    dim3 grid(NN / BN, BB / BM);   // (64, 16)
    gemm_kernel<<<grid, 256, DSMEM_BYTES>>>(labels, labels_s);

    row_loss_kernel<<<BB / 256, 256>>>();
    mean_kernel<<<1, 256>>>(out);
}

// round 7
// speedup vs baseline: 26.1546x; 6.0254x over previous
#include <cuda_runtime.h>
#include <cuda_bf16.h>
#include <math.h>
#include <stdint.h>

// ---------------- problem constants ----------------
#define BB 2048
#define CC 2048
#define NN 16384
#define INV_TEMP 20.0f
#define SCALE_LOG2E 28.853900817779268f   // (1/0.05) * log2(e)

// ---------------- tiling (tcgen05 path) ----------------
#define BM 128
#define BN 256
#define BKC 64                  // bf16 K elems per chunk (128 B per row)
#define NCHUNK (CC / BKC)       // 32
#define NSTAGE 4
#define NSPL 128                // partial slots per row: 64 nblk * 2 halves
#define STAGE_BYTES 49152       // A(16K) + B0(16K) + B1(16K)
#define DSMEM_BYTES (NSTAGE * STAGE_BYTES + 1024)
#define NTHREADS 288            // warps 0-7 load + epilogue, warp 8 = MMA

// ---------------- device scratch ----------------
__device__ __nv_bfloat16 g_A[BB * CC];      // 8 MB
__device__ __nv_bfloat16 g_B[NN * CC];      // 64 MB
__device__ float g_pmin[BB * NSPL];
__device__ float g_nsum[BB * NSPL];
__device__ float g_loss[BB];

// tcgen05 only on arch-specific (sm_103a) pass; generic compute_103 pass gets
// a plain SIMT fallback so ptxas never sees tcgen05 on .target sm_103.
#if defined(__CUDA_ARCH__) && (__CUDA_ARCH__ >= 1000) && \
    (defined(__CUDA_ARCH_FEAT_SM103_ALL) || defined(__CUDA_ARCH_SPECIFIC__) || \
     defined(__CUDA_ARCH_FAMILY_SPECIFIC__))
#define USE_TCGEN05 1
#else
#define USE_TCGEN05 0
#endif

// ---------------- fused fp32 -> bf16 conversion ----------------
#define NA4 (BB * CC / 4)
#define NB4 (NN * CC / 4)
__global__ void cvt_kernel(const float4* __restrict__ A, const float4* __restrict__ B) {
    int i = blockIdx.x * blockDim.x + threadIdx.x;
    if (i < NA4) {
        float4 v = A[i];
        __nv_bfloat162* o = (__nv_bfloat162*)g_A;
        o[2 * i]     = __floats2bfloat162_rn(v.x, v.y);
        o[2 * i + 1] = __floats2bfloat162_rn(v.z, v.w);
    } else if (i < NA4 + NB4) {
        int j = i - NA4;
        float4 v = B[j];
        __nv_bfloat162* o = (__nv_bfloat162*)g_B;
        o[2 * j]     = __floats2bfloat162_rn(v.x, v.y);
        o[2 * j + 1] = __floats2bfloat162_rn(v.z, v.w);
    }
}

#if USE_TCGEN05
// ===========================================================================
// tcgen05 path (sm_103a): warp-specialized 4-stage cp.async pipeline
// ===========================================================================
__device__ __forceinline__ uint32_t smem_u32(const void* p) {
    uint32_t a;
    asm("{ .reg .u64 t; cvta.to.shared.u64 t, %1; cvt.u32.u64 %0, t; }" : "=r"(a) : "l"(p));
    return a;
}
__device__ __forceinline__ uint32_t elect_one() {
    uint32_t p;
    asm volatile("{ .reg .pred p; elect.sync _|p, 0xFFFFFFFF; selp.b32 %0, 1, 0, p; }" : "=r"(p));
    return p;
}
__device__ __forceinline__ float ex2f(float x) {
    float y; asm("ex2.approx.f32 %0, %1;" : "=f"(y) : "f"(x)); return y;
}

#define MBARRIER_INIT(addr, cnt) \
    asm volatile("mbarrier.init.shared.b64 [%0], %1;" :: "r"(addr), "r"(cnt) : "memory")

#define MBARRIER_WAIT_PARITY(addr, par) do {                                   \
    uint32_t _m = (addr), _p = (par), _d;                                      \
    asm volatile("{ .reg .pred p;"                                             \
        "mbarrier.try_wait.parity.acquire.cta.shared::cta.b64 p, [%1], %2;"    \
        "selp.b32 %0, 1, 0, p; }" : "=r"(_d) : "r"(_m), "r"(_p) : "memory");   \
    if (!_d) {                                                                 \
        asm volatile("{ .reg .pred P1; WL_%=:"                                 \
        "mbarrier.try_wait.parity.acquire.cta.shared::cta.b64 P1, [%0], %1, 0x989680;" \
        "@P1 bra.uni WD_%=; bra.uni WL_%=; WD_%=: }"                           \
        :: "r"(_m), "r"(_p) : "memory");                                       \
    }                                                                          \
} while (0)

#define CP_ASYNC16(dst, src) \
    asm volatile("cp.async.cg.shared.global [%0], [%1], 16;" \
                 :: "r"(dst), "l"(src) : "memory")
// .noinc: do NOT bump the pending-arrival count at issue; the async completion
// performs a plain arrive. Barrier is initialized with count = #producer threads.
#define CP_ASYNC_ARRIVE_NOINC(mb) \
    asm volatile("cp.async.mbarrier.arrive.noinc.shared.b64 [%0];" :: "r"(mb) : "memory")

#define TCGEN05_ALLOC(slot, ncols) \
    asm volatile("tcgen05.alloc.cta_group::1.sync.aligned.shared::cta.b32 [%0], %1;" \
                 :: "r"(slot), "r"(ncols) : "memory")
#define TCGEN05_DEALLOC(tmem, ncols) \
    asm volatile("tcgen05.dealloc.cta_group::1.sync.aligned.b32 %0, %1;" :: "r"(tmem), "r"(ncols))
#define TCGEN05_RELINQ() \
    asm volatile("tcgen05.relinquish_alloc_permit.cta_group::1.sync.aligned;")
#define TCGEN05_COMMIT(mb) \
    asm volatile("tcgen05.commit.cta_group::1.mbarrier::arrive::one.shared::cluster.b64 [%0];" \
                 :: "r"(mb) : "memory")
#define TCGEN05_FENCE_AFTER() asm volatile("tcgen05.fence::after_thread_sync;" ::: "memory")
#define TCGEN05_WAIT_LD()     asm volatile("tcgen05.wait::ld.sync.aligned;" ::: "memory")

#define TCGEN05_LD_X32(r, addr) \
    asm volatile("tcgen05.ld.sync.aligned.32x32b.x32.b32 " \
        "{%0,%1,%2,%3,%4,%5,%6,%7,%8,%9,%10,%11,%12,%13,%14,%15," \
        "%16,%17,%18,%19,%20,%21,%22,%23,%24,%25,%26,%27,%28,%29,%30,%31}, [%32];" \
        : "=r"((r)[0]),"=r"((r)[1]),"=r"((r)[2]),"=r"((r)[3]),"=r"((r)[4]),"=r"((r)[5]), \
          "=r"((r)[6]),"=r"((r)[7]),"=r"((r)[8]),"=r"((r)[9]),"=r"((r)[10]),"=r"((r)[11]), \
          "=r"((r)[12]),"=r"((r)[13]),"=r"((r)[14]),"=r"((r)[15]),"=r"((r)[16]),"=r"((r)[17]), \
          "=r"((r)[18]),"=r"((r)[19]),"=r"((r)[20]),"=r"((r)[21]),"=r"((r)[22]),"=r"((r)[23]), \
          "=r"((r)[24]),"=r"((r)[25]),"=r"((r)[26]),"=r"((r)[27]),"=r"((r)[28]),"=r"((r)[29]), \
          "=r"((r)[30]),"=r"((r)[31]) : "r"(addr))

// idesc: f32 accum, bf16 A/B, N=128, M=128
#define IDESC ((1u << 4) | (1u << 7) | (1u << 10) | (16u << 17) | (8u << 24))

__device__ __forceinline__ uint64_t make_desc(uint32_t addr) {
    return (2ull << 61) | (1ull << 46) | (64ull << 32) | (1ull << 16)
         | ((uint64_t)(addr >> 4) & 0x3FFF);
}
__device__ __forceinline__ uint32_t swz(uint32_t o) { return o ^ ((o >> 3) & 0x70); }

__device__ __forceinline__ void mma_f16_ss(uint32_t d, uint64_t a, uint64_t b,
                                           uint32_t idesc, uint32_t acc) {
    asm volatile("{ .reg .pred p; setp.ne.u32 p, %5, 0;"
        "tcgen05.mma.cta_group::1.kind::f16 [%0], %1, %2, %3, {%4,%4,%4,%4}, p; }"
        :: "r"(d), "l"(a), "l"(b), "r"(idesc), "r"(0u), "r"(acc) : "memory");
}

__global__ __launch_bounds__(NTHREADS)
void gemm_kernel(const int* __restrict__ labels, const int* __restrict__ labels_s)
{
    extern __shared__ char dsm[];
    __shared__ uint64_t full_b[NSTAGE], empty_b[NSTAGE], done_b;
    __shared__ uint32_t tmem_slot;
    __shared__ int slab[BN];

    const int nblk = blockIdx.x;           // 0..63
    const int mblk = blockIdx.y;           // 0..15
    const int row0 = mblk * BM;
    const int col0 = nblk * BN;
    const int tid  = threadIdx.x;
    const int wid  = tid >> 5;

    char* sm = (char*)(((uintptr_t)dsm + 1023) & ~(uintptr_t)1023);
    const uint32_t smb = smem_u32(sm);
    const uint32_t done_a = smem_u32(&done_b);

    if (wid == 0) TCGEN05_ALLOC(smem_u32(&tmem_slot), 256);
    if (tid == 0) {
        #pragma unroll
        for (int s = 0; s < NSTAGE; ++s) {
            MBARRIER_INIT(smem_u32(&full_b[s]), 256);
            MBARRIER_INIT(smem_u32(&empty_b[s]), 1);
        }
        MBARRIER_INIT(done_a, 1);
    }
    if (tid < BN) slab[tid] = labels_s[col0 + tid];
    __syncthreads();
    const uint32_t tmem = tmem_slot;

    if (wid < 8) {
        // ------------- producer: 256 threads, cp.async per stage -------------
        const char* asrc[4];
        const char* bsrc[8];
        uint32_t adst[4], bdst[8];
        #pragma unroll
        for (int t = 0; t < 4; ++t) {
            int idx = tid + t * 256;
            int r = idx >> 3, sg = idx & 7;
            asrc[t] = (const char*)(g_A + (size_t)(row0 + r) * CC + sg * 8);
            adst[t] = swz(r * 128 + sg * 16);
        }
        #pragma unroll
        for (int t = 0; t < 8; ++t) {
            int idx = tid + t * 256;
            int r = idx >> 3, sg = idx & 7;
            bsrc[t] = (const char*)(g_B + (size_t)(col0 + r) * CC + sg * 8);
            bdst[t] = 16384 + (r >> 7) * 16384 + swz((r & 127) * 128 + sg * 16);
        }
        for (int k = 0; k < NCHUNK; ++k) {
            const int s = k & 3;
            if (k >= NSTAGE)
                MBARRIER_WAIT_PARITY(smem_u32(&empty_b[s]), ((k - NSTAGE) >> 2) & 1);
            const uint32_t sb = smb + s * STAGE_BYTES;
            const int koff = k * (BKC * 2);   // bytes
            #pragma unroll
            for (int t = 0; t < 4; ++t) CP_ASYNC16(sb + adst[t], asrc[t] + koff);
            #pragma unroll
            for (int t = 0; t < 8; ++t) CP_ASYNC16(sb + bdst[t], bsrc[t] + koff);
            CP_ASYNC_ARRIVE_NOINC(smem_u32(&full_b[s]));
        }
    } else {
        // ------------- MMA issuer: warp 8, elected lane -------------
        if (elect_one()) {
            for (int k = 0; k < NCHUNK; ++k) {
                const int s = k & 3;
                MBARRIER_WAIT_PARITY(smem_u32(&full_b[s]), (k >> 2) & 1);
                asm volatile("fence.proxy.async.shared::cta;" ::: "memory");
                const uint32_t sb = smb + s * STAGE_BYTES;
                uint64_t ad = make_desc(sb);
                uint64_t b0 = make_desc(sb + 16384);
                uint64_t b1 = make_desc(sb + 32768);
                #pragma unroll
                for (int ks = 0; ks < 4; ++ks) {
                    uint32_t acc = (k > 0 || ks > 0) ? 1u : 0u;
                    mma_f16_ss(tmem,       ad + ks * 2, b0 + ks * 2, IDESC, acc);
                    mma_f16_ss(tmem + 128, ad + ks * 2, b1 + ks * 2, IDESC, acc);
                }
                TCGEN05_COMMIT(smem_u32(&empty_b[s]));
            }
            TCGEN05_COMMIT(done_a);
        }
    }

    // ------------- wait for all MMAs, then epilogue -------------
    MBARRIER_WAIT_PARITY(done_a, 0);
    TCGEN05_FENCE_AFTER();

    if (tid < 256) {
        const int half = tid >> 7;
        const int wg   = tid & 127;                       // D row
        const uint32_t woff = (uint32_t)(wg >> 5) << 21;  // TMEM lane-group
        const int lab = labels[row0 + wg];
        const uint32_t dbase = tmem + half * 128 + woff;

        float smin = INFINITY, nsum = 0.0f;
        #pragma unroll
        for (int cb = 0; cb < 4; ++cb) {
            uint32_t regs[32];
            TCGEN05_LD_X32(regs, dbase + cb * 32);
            TCGEN05_WAIT_LD();
            #pragma unroll
            for (int c = 0; c < 32; ++c) {
                float s = __uint_as_float(regs[c]);
                int cl = slab[half * 128 + cb * 32 + c];
                if (cl == lab) smin = fminf(smin, s);
                else           nsum += ex2f(s * SCALE_LOG2E);
            }
        }
        float pmin = ex2f(smin * SCALE_LOG2E);
        size_t slot = (size_t)(row0 + wg) * NSPL + nblk * 2 + half;
        g_pmin[slot] = pmin;
        g_nsum[slot] = nsum;
    }

    __syncthreads();
    if (wid == 0) { TCGEN05_RELINQ(); TCGEN05_DEALLOC(tmem, 256); }
}

#else
// ===========================================================================
// Fallback (plain sm_103 pass only; never selected at runtime on GB300)
// ===========================================================================
__global__ __launch_bounds__(NTHREADS)
void gemm_kernel(const int* __restrict__ labels, const int* __restrict__ labels_s)
{
    __shared__ float As[16][64];
    __shared__ float Bs[16][64];
    __shared__ float red_min[64][16];
    __shared__ float red_sum[64][16];

    const int tid  = threadIdx.x;
    if (tid >= 256) return;    // extra warp exits; Volta+ bar.sync ignores exited
    const int nblk = blockIdx.x;
    const int mblk = blockIdx.y;
    const int tx   = tid & 15;
    const int ty   = tid >> 4;
    const int lr   = tid >> 2;
    const int lk4  = (tid & 3) * 4;

    for (int msub = 0; msub < 2; ++msub) {
        const int row0 = mblk * 128 + msub * 64;
        int labr[4];
        #pragma unroll
        for (int i = 0; i < 4; ++i) labr[i] = labels[row0 + ty * 4 + i];

        for (int half = 0; half < 2; ++half) {
            float fm = INFINITY, fs = 0.0f;
            for (int nsub = 0; nsub < 2; ++nsub) {
                const int col0 = nblk * 256 + half * 128 + nsub * 64;
                int labc[4];
                #pragma unroll
                for (int j = 0; j < 4; ++j) labc[j] = labels_s[col0 + tx * 4 + j];

                float acc[4][4];
                #pragma unroll
                for (int i = 0; i < 4; ++i)
                    #pragma unroll
                    for (int j = 0; j < 4; ++j) acc[i][j] = 0.0f;

                for (int k0 = 0; k0 < CC; k0 += 16) {
                    const __nv_bfloat162* ap = (const __nv_bfloat162*)
                        (g_A + (size_t)(row0 + lr) * CC + k0 + lk4);
                    const __nv_bfloat162* bp = (const __nv_bfloat162*)
                        (g_B + (size_t)(col0 + lr) * CC + k0 + lk4);
                    __nv_bfloat162 a01 = ap[0], a23 = ap[1];
                    __nv_bfloat162 b01 = bp[0], b23 = bp[1];
                    __syncthreads();
                    As[lk4 + 0][lr] = __bfloat162float(a01.x);
                    As[lk4 + 1][lr] = __bfloat162float(a01.y);
                    As[lk4 + 2][lr] = __bfloat162float(a23.x);
                    As[lk4 + 3][lr] = __bfloat162float(a23.y);
                    Bs[lk4 + 0][lr] = __bfloat162float(b01.x);
                    Bs[lk4 + 1][lr] = __bfloat162float(b01.y);
                    Bs[lk4 + 2][lr] = __bfloat162float(b23.x);
                    Bs[lk4 + 3][lr] = __bfloat162float(b23.y);
                    __syncthreads();
                    #pragma unroll
                    for (int kk = 0; kk < 16; ++kk) {
                        float4 a = *(const float4*)&As[kk][ty * 4];
                        float4 b = *(const float4*)&Bs[kk][tx * 4];
                        acc[0][0] += a.x * b.x; acc[0][1] += a.x * b.y;
                        acc[0][2] += a.x * b.z; acc[0][3] += a.x * b.w;
                        acc[1][0] += a.y * b.x; acc[1][1] += a.y * b.y;
                        acc[1][2] += a.y * b.z; acc[1][3] += a.y * b.w;
                        acc[2][0] += a.z * b.x; acc[2][1] += a.z * b.y;
                        acc[2][2] += a.z * b.z; acc[2][3] += a.z * b.w;
                        acc[3][0] += a.w * b.x; acc[3][1] += a.w * b.y;
                        acc[3][2] += a.w * b.z; acc[3][3] += a.w * b.w;
                    }
                }

                #pragma unroll
                for (int i = 0; i < 4; ++i) {
                    float pmin = INFINITY, nsum = 0.0f;
                    #pragma unroll
                    for (int j = 0; j < 4; ++j) {
                        float e = expf(acc[i][j] * INV_TEMP);
                        if (labr[i] == labc[j]) pmin = fminf(pmin, e);
                        else                    nsum += e;
                    }
                    red_min[ty * 4 + i][tx] = pmin;
                    red_sum[ty * 4 + i][tx] = nsum;
                }
                __syncthreads();
                if (tid < 64) {
                    #pragma unroll
                    for (int t = 0; t < 16; ++t) {
                        fm = fminf(fm, red_min[tid][t]);
                        fs += red_sum[tid][t];
                    }
                }
                __syncthreads();
            }
            if (tid < 64) {
                size_t slot = (size_t)(row0 + tid) * NSPL + nblk * 2 + half;
                g_pmin[slot] = fm;
                g_nsum[slot] = fs;
            }
        }
    }
}
#endif  // USE_TCGEN05

// ---------------- per-row loss: one warp per row ----------------
__global__ void row_loss_kernel()
{
    const int lane = threadIdx.x & 31;
    const int row  = (blockIdx.x * blockDim.x + threadIdx.x) >> 5;
    if (row >= BB) return;
    float4 pm = ((const float4*)(g_pmin + (size_t)row * NSPL))[lane];
    float4 ns = ((const float4*)(g_nsum + (size_t)row * NSPL))[lane];
    float m = fminf(fminf(pm.x, pm.y), fminf(pm.z, pm.w));
    float s = (ns.x + ns.y) + (ns.z + ns.w);
    #pragma unroll
    for (int off = 16; off > 0; off >>= 1) {
        m = fminf(m, __shfl_xor_sync(0xFFFFFFFF, m, off));
        s += __shfl_xor_sync(0xFFFFFFFF, s, off);
    }
    if (lane == 0)
        g_loss[row] = -logf(m / (m + s + 1e-6f) + 1e-6f);
}

// ---------------- mean ----------------
__global__ void mean_kernel(float* __restrict__ out)
{
    __shared__ float red[256];
    int tid = threadIdx.x;
    float s = 0.0f;
    for (int r = tid; r < BB; r += 256) s += g_loss[r];
    red[tid] = s;
    __syncthreads();
    for (int off = 128; off > 0; off >>= 1) {
        if (tid < off) red[tid] += red[tid + off];
        __syncthreads();
    }
    if (tid == 0) out[0] = red[0] / (float)BB;
}

extern "C" void kernel_launch(void* const* d_in, const int* in_sizes, int n_in,
                              void* d_out, int out_size)
{
    const float* feats    = (const float*)d_in[0];
    const float* feats_s  = (const float*)d_in[1];
    const int*   labels   = (const int*)d_in[2];
    const int*   labels_s = (const int*)d_in[3];
    float* out = (float*)d_out;

    cudaFuncSetAttribute(gemm_kernel, cudaFuncAttributeMaxDynamicSharedMemorySize,
                         DSMEM_BYTES);

    cvt_kernel<<<(NA4 + NB4 + 255) / 256, 256>>>((const float4*)feats,
                                                 (const float4*)feats_s);
    dim3 grid(NN / BN, BB / BM);   // (64, 16)
    gemm_kernel<<<grid, NTHREADS, DSMEM_BYTES>>>(labels, labels_s);
    row_loss_kernel<<<(BB * 32) / 256, 256>>>();
    mean_kernel<<<1, 256>>>(out);
}

// round 8
// speedup vs baseline: 27.6152x; 1.0558x over previous
#include <cuda_runtime.h>
#include <cuda_bf16.h>
#include <math.h>
#include <stdint.h>

// ---------------- problem constants ----------------
#define BB 2048
#define CC 2048
#define NN 16384
#define INV_TEMP 20.0f
#define SCALE_LOG2E 28.853900817779268f   // (1/0.05) * log2(e)

// ---------------- tiling (tcgen05 path) ----------------
#define BM 256
#define BN 256
#define BKC 64                  // bf16 K elems per chunk (128 B per row)
#define NCHUNK (CC / BKC)       // 32
#define NSTAGE 3
#define NSPL 64                 // partial slots per row = NN/BN
#define STAGE_BYTES 65536       // A0,A1,B0,B1 (16K each)
#define DSMEM_BYTES (NSTAGE * STAGE_BYTES + 1024)
#define NTHREADS 288            // warps 0-7 load + epilogue, warp 8 = MMA

// ---------------- device scratch ----------------
__device__ __nv_bfloat16 g_A[BB * CC];      // 8 MB
__device__ __nv_bfloat16 g_B[NN * CC];      // 64 MB
__device__ float g_pmin[BB * NSPL];
__device__ float g_nsum[BB * NSPL];
__device__ float g_loss[BB];
__device__ int   g_count = 0;

// tcgen05 only on arch-specific (sm_103a) pass; generic compute_103 pass gets
// a plain SIMT fallback so ptxas never sees tcgen05 on .target sm_103.
#if defined(__CUDA_ARCH__) && (__CUDA_ARCH__ >= 1000) && \
    (defined(__CUDA_ARCH_FEAT_SM103_ALL) || defined(__CUDA_ARCH_SPECIFIC__) || \
     defined(__CUDA_ARCH_FAMILY_SPECIFIC__))
#define USE_TCGEN05 1
#else
#define USE_TCGEN05 0
#endif

// ---------------- fused fp32 -> bf16 conversion ----------------
#define NA4 (BB * CC / 4)
#define NB4 (NN * CC / 4)
__global__ void cvt_kernel(const float4* __restrict__ A, const float4* __restrict__ B) {
    int i = blockIdx.x * blockDim.x + threadIdx.x;
    if (i < NA4) {
        float4 v = A[i];
        __nv_bfloat162* o = (__nv_bfloat162*)g_A;
        o[2 * i]     = __floats2bfloat162_rn(v.x, v.y);
        o[2 * i + 1] = __floats2bfloat162_rn(v.z, v.w);
    } else if (i < NA4 + NB4) {
        int j = i - NA4;
        float4 v = B[j];
        __nv_bfloat162* o = (__nv_bfloat162*)g_B;
        o[2 * j]     = __floats2bfloat162_rn(v.x, v.y);
        o[2 * j + 1] = __floats2bfloat162_rn(v.z, v.w);
    }
}

#if USE_TCGEN05
// ===========================================================================
// tcgen05 path (sm_103a): 256x256 tile, warp-specialized 3-stage cp.async
// ===========================================================================
__device__ __forceinline__ uint32_t smem_u32(const void* p) {
    uint32_t a;
    asm("{ .reg .u64 t; cvta.to.shared.u64 t, %1; cvt.u32.u64 %0, t; }" : "=r"(a) : "l"(p));
    return a;
}
__device__ __forceinline__ uint32_t elect_one() {
    uint32_t p;
    asm volatile("{ .reg .pred p; elect.sync _|p, 0xFFFFFFFF; selp.b32 %0, 1, 0, p; }" : "=r"(p));
    return p;
}
__device__ __forceinline__ float ex2f(float x) {
    float y; asm("ex2.approx.f32 %0, %1;" : "=f"(y) : "f"(x)); return y;
}

#define MBARRIER_INIT(addr, cnt) \
    asm volatile("mbarrier.init.shared.b64 [%0], %1;" :: "r"(addr), "r"(cnt) : "memory")

#define MBARRIER_WAIT_PARITY(addr, par) do {                                   \
    uint32_t _m = (addr), _p = (par), _d;                                      \
    asm volatile("{ .reg .pred p;"                                             \
        "mbarrier.try_wait.parity.acquire.cta.shared::cta.b64 p, [%1], %2;"    \
        "selp.b32 %0, 1, 0, p; }" : "=r"(_d) : "r"(_m), "r"(_p) : "memory");   \
    if (!_d) {                                                                 \
        asm volatile("{ .reg .pred P1; WL_%=:"                                 \
        "mbarrier.try_wait.parity.acquire.cta.shared::cta.b64 P1, [%0], %1, 0x989680;" \
        "@P1 bra.uni WD_%=; bra.uni WL_%=; WD_%=: }"                           \
        :: "r"(_m), "r"(_p) : "memory");                                       \
    }                                                                          \
} while (0)

#define CP_ASYNC16(dst, src) \
    asm volatile("cp.async.cg.shared.global [%0], [%1], 16;" \
                 :: "r"(dst), "l"(src) : "memory")
#define CP_ASYNC_ARRIVE_NOINC(mb) \
    asm volatile("cp.async.mbarrier.arrive.noinc.shared.b64 [%0];" :: "r"(mb) : "memory")

#define TCGEN05_ALLOC(slot, ncols) \
    asm volatile("tcgen05.alloc.cta_group::1.sync.aligned.shared::cta.b32 [%0], %1;" \
                 :: "r"(slot), "r"(ncols) : "memory")
#define TCGEN05_DEALLOC(tmem, ncols) \
    asm volatile("tcgen05.dealloc.cta_group::1.sync.aligned.b32 %0, %1;" :: "r"(tmem), "r"(ncols))
#define TCGEN05_RELINQ() \
    asm volatile("tcgen05.relinquish_alloc_permit.cta_group::1.sync.aligned;")
#define TCGEN05_COMMIT(mb) \
    asm volatile("tcgen05.commit.cta_group::1.mbarrier::arrive::one.shared::cluster.b64 [%0];" \
                 :: "r"(mb) : "memory")
#define TCGEN05_FENCE_AFTER() asm volatile("tcgen05.fence::after_thread_sync;" ::: "memory")
#define TCGEN05_WAIT_LD()     asm volatile("tcgen05.wait::ld.sync.aligned;" ::: "memory")

#define TCGEN05_LD_X32(r, addr) \
    asm volatile("tcgen05.ld.sync.aligned.32x32b.x32.b32 " \
        "{%0,%1,%2,%3,%4,%5,%6,%7,%8,%9,%10,%11,%12,%13,%14,%15," \
        "%16,%17,%18,%19,%20,%21,%22,%23,%24,%25,%26,%27,%28,%29,%30,%31}, [%32];" \
        : "=r"((r)[0]),"=r"((r)[1]),"=r"((r)[2]),"=r"((r)[3]),"=r"((r)[4]),"=r"((r)[5]), \
          "=r"((r)[6]),"=r"((r)[7]),"=r"((r)[8]),"=r"((r)[9]),"=r"((r)[10]),"=r"((r)[11]), \
          "=r"((r)[12]),"=r"((r)[13]),"=r"((r)[14]),"=r"((r)[15]),"=r"((r)[16]),"=r"((r)[17]), \
          "=r"((r)[18]),"=r"((r)[19]),"=r"((r)[20]),"=r"((r)[21]),"=r"((r)[22]),"=r"((r)[23]), \
          "=r"((r)[24]),"=r"((r)[25]),"=r"((r)[26]),"=r"((r)[27]),"=r"((r)[28]),"=r"((r)[29]), \
          "=r"((r)[30]),"=r"((r)[31]) : "r"(addr))

// idesc: f32 accum, bf16 A/B, N=128, M=128
#define IDESC ((1u << 4) | (1u << 7) | (1u << 10) | (16u << 17) | (8u << 24))

__device__ __forceinline__ uint64_t make_desc(uint32_t addr) {
    return (2ull << 61) | (1ull << 46) | (64ull << 32) | (1ull << 16)
         | ((uint64_t)(addr >> 4) & 0x3FFF);
}
__device__ __forceinline__ uint32_t swz(uint32_t o) { return o ^ ((o >> 3) & 0x70); }

__device__ __forceinline__ void mma_f16_ss(uint32_t d, uint64_t a, uint64_t b,
                                           uint32_t idesc, uint32_t acc) {
    asm volatile("{ .reg .pred p; setp.ne.u32 p, %5, 0;"
        "tcgen05.mma.cta_group::1.kind::f16 [%0], %1, %2, %3, {%4,%4,%4,%4}, p; }"
        :: "r"(d), "l"(a), "l"(b), "r"(idesc), "r"(0u), "r"(acc) : "memory");
}

__global__ __launch_bounds__(NTHREADS)
void gemm_kernel(const int* __restrict__ labels, const int* __restrict__ labels_s)
{
    extern __shared__ char dsm[];
    __shared__ uint64_t full_b[NSTAGE], empty_b[NSTAGE], done_b;
    __shared__ uint32_t tmem_slot;
    __shared__ int slab[BN];

    const int nblk = blockIdx.x;           // 0..63
    const int mblk = blockIdx.y;           // 0..7
    const int row0 = mblk * BM;
    const int col0 = nblk * BN;
    const int tid  = threadIdx.x;
    const int wid  = tid >> 5;

    char* sm = (char*)(((uintptr_t)dsm + 1023) & ~(uintptr_t)1023);
    const uint32_t smb = smem_u32(sm);
    const uint32_t done_a = smem_u32(&done_b);

    if (wid == 0) TCGEN05_ALLOC(smem_u32(&tmem_slot), 512);
    if (tid == 0) {
        #pragma unroll
        for (int s = 0; s < NSTAGE; ++s) {
            MBARRIER_INIT(smem_u32(&full_b[s]), 256);
            MBARRIER_INIT(smem_u32(&empty_b[s]), 1);
        }
        MBARRIER_INIT(done_a, 1);
    }
    if (tid < BN) slab[tid] = labels_s[col0 + tid];
    __syncthreads();
    const uint32_t tmem = tmem_slot;

    if (wid < 8) {
        // --------- producer: 256 threads, 16 x cp.async16 per chunk ---------
        // stage layout: A0 @0, A1 @16K, B0 @32K, B1 @48K; rows 128B SW128
        const char* srcs[16];
        uint32_t dsts[16];
        #pragma unroll
        for (int t = 0; t < 16; ++t) {
            int idx = tid + t * 256;          // 0..4095
            if (idx < 2048) {                 // A rows 0..255
                int r = idx >> 3, sg = idx & 7;
                srcs[t] = (const char*)(g_A + (size_t)(row0 + r) * CC + sg * 8);
                dsts[t] = (r >> 7) * 16384 + swz((r & 127) * 128 + sg * 16);
            } else {                          // B rows 0..255
                int i2 = idx - 2048;
                int r = i2 >> 3, sg = i2 & 7;
                srcs[t] = (const char*)(g_B + (size_t)(col0 + r) * CC + sg * 8);
                dsts[t] = 32768 + (r >> 7) * 16384 + swz((r & 127) * 128 + sg * 16);
            }
        }
        int s = 0, u = 0;
        for (int k = 0; k < NCHUNK; ++k) {
            if (u > 0) MBARRIER_WAIT_PARITY(smem_u32(&empty_b[s]), (u - 1) & 1);
            const uint32_t sb = smb + s * STAGE_BYTES;
            const int koff = k * (BKC * 2);   // bytes along K
            #pragma unroll
            for (int t = 0; t < 16; ++t) CP_ASYNC16(sb + dsts[t], srcs[t] + koff);
            CP_ASYNC_ARRIVE_NOINC(smem_u32(&full_b[s]));
            if (++s == NSTAGE) { s = 0; ++u; }
        }
    } else {
        // --------- MMA issuer: warp 8, elected lane ---------
        if (elect_one()) {
            int s = 0, u = 0;
            for (int k = 0; k < NCHUNK; ++k) {
                MBARRIER_WAIT_PARITY(smem_u32(&full_b[s]), u & 1);
                asm volatile("fence.proxy.async.shared::cta;" ::: "memory");
                const uint32_t sb = smb + s * STAGE_BYTES;
                uint64_t a0 = make_desc(sb);
                uint64_t a1 = make_desc(sb + 16384);
                uint64_t b0 = make_desc(sb + 32768);
                uint64_t b1 = make_desc(sb + 49152);
                #pragma unroll
                for (int ks = 0; ks < 4; ++ks) {
                    uint32_t acc = (k > 0 || ks > 0) ? 1u : 0u;
                    mma_f16_ss(tmem,       a0 + ks * 2, b0 + ks * 2, IDESC, acc);
                    mma_f16_ss(tmem + 128, a0 + ks * 2, b1 + ks * 2, IDESC, acc);
                    mma_f16_ss(tmem + 256, a1 + ks * 2, b0 + ks * 2, IDESC, acc);
                    mma_f16_ss(tmem + 384, a1 + ks * 2, b1 + ks * 2, IDESC, acc);
                }
                TCGEN05_COMMIT(smem_u32(&empty_b[s]));
                if (++s == NSTAGE) { s = 0; ++u; }
            }
            TCGEN05_COMMIT(done_a);
        }
    }

    // --------- wait for all MMAs, then epilogue ---------
    MBARRIER_WAIT_PARITY(done_a, 0);
    TCGEN05_FENCE_AFTER();

    if (tid < 256) {
        const int mh = tid >> 7;                          // M-half
        const int wg = tid & 127;                         // lane row in half
        const uint32_t woff = (uint32_t)(wg >> 5) << 21;  // TMEM lane-group
        const int rowg = row0 + mh * 128 + wg;
        const int lab = labels[rowg];
        const uint32_t dbase = tmem + mh * 256 + woff;

        float smin = INFINITY, nsum = 0.0f;
        #pragma unroll
        for (int cb = 0; cb < 8; ++cb) {
            uint32_t regs[32];
            TCGEN05_LD_X32(regs, dbase + cb * 32);
            TCGEN05_WAIT_LD();
            #pragma unroll
            for (int c = 0; c < 32; ++c) {
                float sv = __uint_as_float(regs[c]);
                int cl = slab[cb * 32 + c];
                if (cl == lab) smin = fminf(smin, sv);
                else           nsum += ex2f(sv * SCALE_LOG2E);
            }
        }
        float pmin = ex2f(smin * SCALE_LOG2E);
        size_t slot = (size_t)rowg * NSPL + nblk;
        g_pmin[slot] = pmin;
        g_nsum[slot] = nsum;
    }

    __syncthreads();
    if (wid == 0) { TCGEN05_RELINQ(); TCGEN05_DEALLOC(tmem, 512); }
}

#else
// ===========================================================================
// Fallback (plain sm_103 pass only; never selected at runtime on GB300)
// ===========================================================================
__global__ __launch_bounds__(NTHREADS)
void gemm_kernel(const int* __restrict__ labels, const int* __restrict__ labels_s)
{
    __shared__ float As[16][64];
    __shared__ float Bs[16][64];
    __shared__ float red_min[64][16];
    __shared__ float red_sum[64][16];

    const int tid  = threadIdx.x;
    if (tid >= 256) return;
    const int nblk = blockIdx.x;   // 0..63
    const int mblk = blockIdx.y;   // 0..7
    const int tx   = tid & 15;
    const int ty   = tid >> 4;
    const int lr   = tid >> 2;
    const int lk4  = (tid & 3) * 4;

    for (int msub = 0; msub < 4; ++msub) {
        const int row0 = mblk * BM + msub * 64;
        int labr[4];
        #pragma unroll
        for (int i = 0; i < 4; ++i) labr[i] = labels[row0 + ty * 4 + i];

        float fm = INFINITY, fs = 0.0f;
        for (int nsub = 0; nsub < 4; ++nsub) {
            const int col0 = nblk * BN + nsub * 64;
            int labc[4];
            #pragma unroll
            for (int j = 0; j < 4; ++j) labc[j] = labels_s[col0 + tx * 4 + j];

            float acc[4][4];
            #pragma unroll
            for (int i = 0; i < 4; ++i)
                #pragma unroll
                for (int j = 0; j < 4; ++j) acc[i][j] = 0.0f;

            for (int k0 = 0; k0 < CC; k0 += 16) {
                const __nv_bfloat162* ap = (const __nv_bfloat162*)
                    (g_A + (size_t)(row0 + lr) * CC + k0 + lk4);
                const __nv_bfloat162* bp = (const __nv_bfloat162*)
                    (g_B + (size_t)(col0 + lr) * CC + k0 + lk4);
                __nv_bfloat162 a01 = ap[0], a23 = ap[1];
                __nv_bfloat162 b01 = bp[0], b23 = bp[1];
                __syncthreads();
                As[lk4 + 0][lr] = __bfloat162float(a01.x);
                As[lk4 + 1][lr] = __bfloat162float(a01.y);
                As[lk4 + 2][lr] = __bfloat162float(a23.x);
                As[lk4 + 3][lr] = __bfloat162float(a23.y);
                Bs[lk4 + 0][lr] = __bfloat162float(b01.x);
                Bs[lk4 + 1][lr] = __bfloat162float(b01.y);
                Bs[lk4 + 2][lr] = __bfloat162float(b23.x);
                Bs[lk4 + 3][lr] = __bfloat162float(b23.y);
                __syncthreads();
                #pragma unroll
                for (int kk = 0; kk < 16; ++kk) {
                    float4 a = *(const float4*)&As[kk][ty * 4];
                    float4 b = *(const float4*)&Bs[kk][tx * 4];
                    acc[0][0] += a.x * b.x; acc[0][1] += a.x * b.y;
                    acc[0][2] += a.x * b.z; acc[0][3] += a.x * b.w;
                    acc[1][0] += a.y * b.x; acc[1][1] += a.y * b.y;
                    acc[1][2] += a.y * b.z; acc[1][3] += a.y * b.w;
                    acc[2][0] += a.z * b.x; acc[2][1] += a.z * b.y;
                    acc[2][2] += a.z * b.z; acc[2][3] += a.z * b.w;
                    acc[3][0] += a.w * b.x; acc[3][1] += a.w * b.y;
                    acc[3][2] += a.w * b.z; acc[3][3] += a.w * b.w;
                }
            }

            #pragma unroll
            for (int i = 0; i < 4; ++i) {
                float pmin = INFINITY, nsum = 0.0f;
                #pragma unroll
                for (int j = 0; j < 4; ++j) {
                    float e = expf(acc[i][j] * INV_TEMP);
                    if (labr[i] == labc[j]) pmin = fminf(pmin, e);
                    else                    nsum += e;
                }
                red_min[ty * 4 + i][tx] = pmin;
                red_sum[ty * 4 + i][tx] = nsum;
            }
            __syncthreads();
            if (tid < 64) {
                #pragma unroll
                for (int t = 0; t < 16; ++t) {
                    fm = fminf(fm, red_min[tid][t]);
                    fs += red_sum[tid][t];
                }
            }
            __syncthreads();
        }
        if (tid < 64) {
            size_t slot = (size_t)(row0 + tid) * NSPL + nblk;
            g_pmin[slot] = fm;
            g_nsum[slot] = fs;
        }
    }
}
#endif  // USE_TCGEN05

// ---------------- fused per-row loss + mean (last-block reduction) ----------
__global__ void loss_kernel(float* __restrict__ out)
{
    __shared__ float red[256];
    __shared__ int amLast;
    const int tid  = threadIdx.x;
    const int lane = tid & 31;
    const int row  = blockIdx.x * 8 + (tid >> 5);

    float2 pm = ((const float2*)(g_pmin + (size_t)row * NSPL))[lane];
    float2 ns = ((const float2*)(g_nsum + (size_t)row * NSPL))[lane];
    float m = fminf(pm.x, pm.y);
    float s = ns.x + ns.y;
    #pragma unroll
    for (int off = 16; off > 0; off >>= 1) {
        m = fminf(m, __shfl_xor_sync(0xFFFFFFFF, m, off));
        s += __shfl_xor_sync(0xFFFFFFFF, s, off);
    }
    if (lane == 0)
        g_loss[row] = -logf(m / (m + s + 1e-6f) + 1e-6f);

    __threadfence();
    __syncthreads();
    if (tid == 0) amLast = (atomicAdd(&g_count, 1) == (BB / 8) - 1);
    __syncthreads();
    if (amLast) {
        __threadfence();
        float s2 = 0.0f;
        for (int r = tid; r < BB; r += 256) s2 += g_loss[r];
        red[tid] = s2;
        __syncthreads();
        for (int off = 128; off > 0; off >>= 1) {
            if (tid < off) red[tid] += red[tid + off];
            __syncthreads();
        }
        if (tid == 0) { out[0] = red[0] / (float)BB; g_count = 0; }
    }
}

extern "C" void kernel_launch(void* const* d_in, const int* in_sizes, int n_in,
                              void* d_out, int out_size)
{
    const float* feats    = (const float*)d_in[0];
    const float* feats_s  = (const float*)d_in[1];
    const int*   labels   = (const int*)d_in[2];
    const int*   labels_s = (const int*)d_in[3];
    float* out = (float*)d_out;

    cudaFuncSetAttribute(gemm_kernel, cudaFuncAttributeMaxDynamicSharedMemorySize,
                         DSMEM_BYTES);

    cvt_kernel<<<(NA4 + NB4 + 255) / 256, 256>>>((const float4*)feats,
                                                 (const float4*)feats_s);
    dim3 grid(NN / BN, BB / BM);   // (64, 8)
    gemm_kernel<<<grid, NTHREADS, DSMEM_BYTES>>>(labels, labels_s);
    loss_kernel<<<BB / 8, 256>>>(out);
}